// round 12
// baseline (speedup 1.0000x reference)
#include <cuda_runtime.h>
#include <cstdint>
#include <math.h>

// RetNet retention, chunked-state form. R12: 3-kernel split.
//  A : T[j] = sum_m gamma^(128-m_loc) K[m] (x) V[m]          (unchanged)
//  C1: off-diagonal MSR stream. BM=128, 256thr/8warps, <=85 regs, 3 CTAs/SM.
//  C2: diagonal MSR + intra P@V + inter Q@State + zero-fill.
#define Bsz 2
#define Hn 16
#define Sn 2048
#define DHn 64
#define BM 128
#define BN 128
#define NT 16
#define KS_STRIDE 72
#define ST_STRIDE 72

__device__ float g_T[(size_t)Bsz * Hn * NT * DHn * DHn];   // 8 MB scratch

__device__ __forceinline__ unsigned f2tf(float f) {
    unsigned r; asm("cvt.rna.tf32.f32 %0, %1;" : "=r"(r) : "f"(f)); return r;
}

__device__ __forceinline__ void mma_tf32(float c[4], unsigned a0, unsigned a1,
                                         unsigned a2, unsigned a3, unsigned b0, unsigned b1) {
    asm volatile("mma.sync.aligned.m16n8k8.row.col.f32.tf32.tf32.f32 "
                 "{%0,%1,%2,%3}, {%4,%5,%6,%7}, {%8,%9}, {%0,%1,%2,%3};\n"
                 : "+f"(c[0]), "+f"(c[1]), "+f"(c[2]), "+f"(c[3])
                 : "r"(a0), "r"(a1), "r"(a2), "r"(a3), "r"(b0), "r"(b1));
}

// ---------------- kernel A ----------------
__global__ __launch_bounds__(256, 1)
void state_tiles_kernel(const float* __restrict__ K, const float* __restrict__ V) {
    extern __shared__ float smemA[];
    float* Ks = smemA;
    float* Vs = Ks + BN * 72;
    const int tid = threadIdx.x, warp = tid >> 5, lane = tid & 31;
    const int gr = lane >> 2, tg = lane & 3;
    const int rowA = (warp & 3) * 16, n0 = (warp >> 2) * 32;
    const int jt = blockIdx.x, bh = blockIdx.y, h = bh % Hn, k0 = jt * BN;
    const double epsd = ldexp(1.0, -5 - h);
    const float l2g = (float)(log1p(-epsd) * 1.4426950408889634);
    const float* Kg = K + ((size_t)bh * Sn + k0) * DHn;
    const float* Vg = V + ((size_t)bh * Sn + k0) * DHn;

    for (int i = 0; i < 8; i++) {
        const int idx = tid + i * 256, r = idx >> 4, c = (idx & 15) << 2;
        const float w = exp2f((float)(128 - r) * l2g);
        float4 kv = *(const float4*)(Kg + (size_t)r * DHn + c);
        unsigned* kd = (unsigned*)(Ks + r * 72 + c);
        kd[0] = f2tf(w * kv.x); kd[1] = f2tf(w * kv.y);
        kd[2] = f2tf(w * kv.z); kd[3] = f2tf(w * kv.w);
        float4 vv = *(const float4*)(Vg + (size_t)r * DHn + c);
        unsigned* vd = (unsigned*)(Vs + r * 72 + c);
        vd[0] = f2tf(vv.x); vd[1] = f2tf(vv.y); vd[2] = f2tf(vv.z); vd[3] = f2tf(vv.w);
    }
    __syncthreads();

    float acc[4][4];
    #pragma unroll
    for (int j = 0; j < 4; j++)
        #pragma unroll
        for (int i = 0; i < 4; i++) acc[j][i] = 0.f;
    const unsigned* k32 = (const unsigned*)Ks;
    const unsigned* v32 = (const unsigned*)Vs;
    #pragma unroll
    for (int kk = 0; kk < 16; kk++) {
        const int m = kk * 8 + tg;
        unsigned a0 = k32[m * 72 + rowA + gr],       a1 = k32[m * 72 + rowA + gr + 8];
        unsigned a2 = k32[(m + 4) * 72 + rowA + gr], a3 = k32[(m + 4) * 72 + rowA + gr + 8];
        #pragma unroll
        for (int j = 0; j < 4; j++) {
            unsigned b0 = v32[m * 72 + n0 + j * 8 + gr];
            unsigned b1 = v32[(m + 4) * 72 + n0 + j * 8 + gr];
            mma_tf32(acc[j], a0, a1, a2, a3, b0, b1);
        }
    }
    float* T = g_T + (((size_t)bh * NT + jt) * DHn) * DHn;
    #pragma unroll
    for (int j = 0; j < 4; j++) {
        const int col = n0 + j * 8 + tg * 2;
        *(float2*)(T + (rowA + gr) * DHn + col)     = make_float2(acc[j][0], acc[j][1]);
        *(float2*)(T + (rowA + gr + 8) * DHn + col) = make_float2(acc[j][2], acc[j][3]);
    }
}

// ---------------- kernel C1: off-diagonal MSR stream ----------------
__global__ __launch_bounds__(256, 3)
void msr_stream_kernel(const float* __restrict__ Q, const float* __restrict__ K,
                       float* __restrict__ MSR) {
    extern __shared__ float smem[];
    float* Ks0 = smem;                 // [128][72]
    float* Ks1 = smem + 9216;          // [128][72]

    const int tid = threadIdx.x, warp = tid >> 5, lane = tid & 31;
    const int gr = lane >> 2, tg = lane & 3;
    const int row0 = warp * 16;        // 8 warps cover 128 q-rows

    const int qblk = 15 - blockIdx.x;  // 15..1, heavy first
    const int bh = blockIdx.y, h = bh % Hn;
    const int q0 = qblk * BM;

    const float* Qg = Q + ((size_t)bh * Sn + q0) * DHn;
    const float* Kg = K + (size_t)bh * Sn * DHn;
    float* Mg = MSR + ((size_t)bh * Sn + q0) * Sn;

    const double epsd = ldexp(1.0, -5 - h);
    const float l2g = (float)(log1p(-epsd) * 1.4426950408889634);
    const float pr0 = exp2f((float)(q0 + row0 + gr) * l2g);
    const float pr1 = exp2f((float)(q0 + row0 + gr + 8) * l2g);
    const float g1i = exp2f(-l2g);
    const float g8i = exp2f(-8.0f * l2g);

    const int lr = tid >> 4, c0 = (tid & 15) << 2;
    const int pbase = (c0 & ~7) | ((c0 >> 2) & 1);

    // prologue: Q -> Ks1, K tile0 -> Ks0 (both perm)
    #pragma unroll
    for (int i = 0; i < 8; i++) {
        const int r = lr + i * 16;
        float4 qv = *(const float4*)(Qg + (size_t)r * DHn + c0);
        unsigned* qd = (unsigned*)(Ks1 + r * KS_STRIDE + pbase);
        qd[0] = f2tf(qv.x); qd[2] = f2tf(qv.y); qd[4] = f2tf(qv.z); qd[6] = f2tf(qv.w);
        float4 kv = *(const float4*)(Kg + (size_t)r * DHn + c0);
        unsigned* kd = (unsigned*)(Ks0 + r * KS_STRIDE + pbase);
        kd[0] = f2tf(kv.x); kd[2] = f2tf(kv.y); kd[4] = f2tf(kv.z); kd[6] = f2tf(kv.w);
    }
    __syncthreads();

    // hoist Q A-frags (rows row0..row0+15)
    uint2 qA[8], qB[8];
    #pragma unroll
    for (int kk = 0; kk < 8; kk++) {
        const int fc = kk * 8 + tg * 2;
        qA[kk] = *(const uint2*)(Ks1 + (row0 + gr) * KS_STRIDE + fc);
        qB[kk] = *(const uint2*)(Ks1 + (row0 + gr + 8) * KS_STRIDE + fc);
    }
    __syncthreads();   // Ks1 free for staging

    // running decay: rj = gamma^-(16*j_seq + tg*2), continued across tiles
    float rj = exp2f(-(float)(tg * 2) * l2g);

    for (int kt = 0; kt < qblk; kt++) {
        const float* Ksb = (kt & 1) ? Ks1 : Ks0;
        float* Ksn = (kt & 1) ? Ks0 : Ks1;
        const int k0 = kt * BN;
        const bool pf = (kt + 1 < qblk);
        float* mg = Mg + k0;
        const int r0 = row0 + gr, r1 = r0 + 8;

        float4 kp[4];
        if (pf) {   // chunk A rows 0..63 of next K tile
            const float* kg = Kg + (size_t)(k0 + BN) * DHn;
            #pragma unroll
            for (int i = 0; i < 4; i++)
                kp[i] = *(const float4*)(kg + (size_t)(lr + i * 16) * DHn + c0);
        }

        #pragma unroll
        for (int qq = 0; qq < 4; qq++) {
            // gemm1 quarter: keys qq*32 + j*8 (+gr), j=0..3
            float Sa[4][4];
            #pragma unroll
            for (int j = 0; j < 4; j++)
                #pragma unroll
                for (int i = 0; i < 4; i++) Sa[j][i] = 0.f;
            #pragma unroll
            for (int kk = 0; kk < 8; kk++) {
                const int fc = kk * 8 + tg * 2;
                #pragma unroll
                for (int j = 0; j < 4; j++) {
                    uint2 b = *(const uint2*)(Ksb + (qq * 32 + j * 8 + gr) * KS_STRIDE + fc);
                    mma_tf32(Sa[j], qA[kk].x, qB[kk].x, qA[kk].y, qB[kk].y, b.x, b.y);
                }
            }
            // decay + MSR store
            #pragma unroll
            for (int j = 0; j < 4; j++) {
                const int col = qq * 32 + j * 8 + tg * 2;
                const float dx = rj, dy = rj * g1i;
                float2 p0 = make_float2(Sa[j][0] * (pr0 * dx), Sa[j][1] * (pr0 * dy));
                float2 p1 = make_float2(Sa[j][2] * (pr1 * dx), Sa[j][3] * (pr1 * dy));
                *(float2*)(mg + (size_t)r0 * Sn + col) = p0;
                *(float2*)(mg + (size_t)r1 * Sn + col) = p1;
                rj *= g8i;
            }
            // mid-tile staging: STS chunk A, LDG chunk B
            if (qq == 1 && pf) {
                #pragma unroll
                for (int i = 0; i < 4; i++) {
                    unsigned* kd = (unsigned*)(Ksn + (lr + i * 16) * KS_STRIDE + pbase);
                    kd[0] = f2tf(kp[i].x); kd[2] = f2tf(kp[i].y);
                    kd[4] = f2tf(kp[i].z); kd[6] = f2tf(kp[i].w);
                }
                const float* kg = Kg + (size_t)(k0 + BN) * DHn;
                #pragma unroll
                for (int i = 0; i < 4; i++)
                    kp[i] = *(const float4*)(kg + (size_t)(lr + 64 + i * 16) * DHn + c0);
            }
        }
        if (pf) {   // STS chunk B
            #pragma unroll
            for (int i = 0; i < 4; i++) {
                unsigned* kd = (unsigned*)(Ksn + (lr + 64 + i * 16) * KS_STRIDE + pbase);
                kd[0] = f2tf(kp[i].x); kd[2] = f2tf(kp[i].y);
                kd[4] = f2tf(kp[i].z); kd[6] = f2tf(kp[i].w);
            }
        }
        __syncthreads();
    }
}

// ---------------- kernel C2: diag MSR + intra + inter + zero-fill ----------------
__global__ __launch_bounds__(256, 1)
void retnet_tail_kernel(const float* __restrict__ Q, const float* __restrict__ K,
                        const float* __restrict__ V,
                        float* __restrict__ Out, float* __restrict__ MSR) {
    extern __shared__ float smem[];
    float* Qp  = smem;                  // [128][72] perm Q
    float* Kd  = smem + 9216;           // [128][72] perm K diag
    float* Vd  = smem + 18432;          // [128][72] V diag, 32-group
    float* Sts = smem + 27648;          // [64][72] State fp32

    const int tid = threadIdx.x, warp = tid >> 5, lane = tid & 31;
    const int gr = lane >> 2, tg = lane & 3;
    const int row0 = warp * 16;

    const int qblk = blockIdx.x;       // 0..15
    const int bh = blockIdx.y, h = bh % Hn;
    const int q0 = qblk * BM;

    const float* Qg = Q + ((size_t)bh * Sn + q0) * DHn;
    const float* Kg = K + ((size_t)bh * Sn + q0) * DHn;   // diag: keys at q0
    const float* Vg = V + ((size_t)bh * Sn + q0) * DHn;
    float* Og = Out + ((size_t)bh * Sn + q0) * DHn;
    float* Mg = MSR + ((size_t)bh * Sn + q0) * Sn;

    const double epsd = ldexp(1.0, -5 - h);
    const float l2g = (float)(log1p(-epsd) * 1.4426950408889634);
    const float pr0 = exp2f((float)(q0 + row0 + gr) * l2g);
    const float pr1 = exp2f((float)(q0 + row0 + gr + 8) * l2g);
    const float g1i = exp2f(-l2g);
    const float g8i = exp2f(-8.0f * l2g);

    const int lr = tid >> 4, c0 = (tid & 15) << 2;
    const int pbase = (c0 & ~7) | ((c0 >> 2) & 1);
    const int vc0 = ((c0 & 7) * 4) + ((c0 & 31) >> 3) + (c0 & ~31);

    // stage Q, Kd, Vd
    #pragma unroll
    for (int i = 0; i < 8; i++) {
        const int r = lr + i * 16;
        float4 qv = *(const float4*)(Qg + (size_t)r * DHn + c0);
        unsigned* qd = (unsigned*)(Qp + r * KS_STRIDE + pbase);
        qd[0] = f2tf(qv.x); qd[2] = f2tf(qv.y); qd[4] = f2tf(qv.z); qd[6] = f2tf(qv.w);
        float4 kv = *(const float4*)(Kg + (size_t)r * DHn + c0);
        unsigned* kd = (unsigned*)(Kd + r * KS_STRIDE + pbase);
        kd[0] = f2tf(kv.x); kd[2] = f2tf(kv.y); kd[4] = f2tf(kv.z); kd[6] = f2tf(kv.w);
        float4 vv = *(const float4*)(Vg + (size_t)r * DHn + c0);
        unsigned* vd = (unsigned*)(Vd + r * KS_STRIDE + vc0);
        vd[0] = f2tf(vv.x); vd[4] = f2tf(vv.y); vd[8] = f2tf(vv.z); vd[12] = f2tf(vv.w);
    }
    // state combine: T[j], j < qblk, weight gamma^(q0 - 128(j+1))
    {
        const int sdp = tid >> 2, sdc = (tid & 3) << 4;
        float sa[16];
        #pragma unroll
        for (int i = 0; i < 16; i++) sa[i] = 0.f;
        for (int j = 0; j < qblk; j++) {
            const float w = exp2f((float)(q0 - BN * (j + 1)) * l2g);
            const float4* tp =
                (const float4*)(g_T + (((size_t)bh * NT + j) * DHn + sdp) * DHn + sdc);
            #pragma unroll
            for (int t = 0; t < 4; t++) {
                float4 ta = tp[t];
                sa[t*4+0] += w * ta.x; sa[t*4+1] += w * ta.y;
                sa[t*4+2] += w * ta.z; sa[t*4+3] += w * ta.w;
            }
        }
        #pragma unroll
        for (int t = 0; t < 4; t++)
            *(float4*)(Sts + sdp * ST_STRIDE + sdc + t * 4) =
                make_float4(sa[t*4+0], sa[t*4+1], sa[t*4+2], sa[t*4+3]);
    }
    __syncthreads();

    // hoist Q frags
    uint2 qA[8], qB[8];
    #pragma unroll
    for (int kk = 0; kk < 8; kk++) {
        const int fc = kk * 8 + tg * 2;
        qA[kk] = *(const uint2*)(Qp + (row0 + gr) * KS_STRIDE + fc);
        qB[kk] = *(const uint2*)(Qp + (row0 + gr + 8) * KS_STRIDE + fc);
    }

    float Oa[8][4];
    #pragma unroll
    for (int j = 0; j < 8; j++)
        #pragma unroll
        for (int i = 0; i < 4; i++) Oa[j][i] = 0.f;

    const int srcA = (lane & ~3) | (tg >> 1);
    const int srcB = srcA + 2;
    const int r0 = row0 + gr, r1 = r0 + 8;

    // two 64-key halves: gemm1 + masked decay + MSR + intra
    #pragma unroll
    for (int jh = 0; jh < 2; jh++) {
        float Sa[8][4];
        #pragma unroll
        for (int j = 0; j < 8; j++)
            #pragma unroll
            for (int i = 0; i < 4; i++) Sa[j][i] = 0.f;
        #pragma unroll
        for (int kk = 0; kk < 8; kk++) {
            const int fc = kk * 8 + tg * 2;
            #pragma unroll
            for (int j = 0; j < 8; j++) {
                uint2 b = *(const uint2*)(Kd + (jh * 64 + j * 8 + gr) * KS_STRIDE + fc);
                mma_tf32(Sa[j], qA[kk].x, qB[kk].x, qA[kk].y, qB[kk].y, b.x, b.y);
            }
        }
        unsigned Pr[8][4];
        float rj = exp2f(-(float)(q0 + jh * 64 + tg * 2) * l2g);
        #pragma unroll
        for (int j = 0; j < 8; j++) {
            const int col = jh * 64 + j * 8 + tg * 2;   // local key col
            const float dx = rj, dy = rj * g1i;
            float d00 = pr0 * dx, d01 = pr0 * dy;
            float d10 = pr1 * dx, d11 = pr1 * dy;
            if (r0 < col)     d00 = 0.f;
            if (r0 < col + 1) d01 = 0.f;
            if (r1 < col)     d10 = 0.f;
            if (r1 < col + 1) d11 = 0.f;
            float2 p0 = make_float2(Sa[j][0] * d00, Sa[j][1] * d01);
            float2 p1 = make_float2(Sa[j][2] * d10, Sa[j][3] * d11);
            *(float2*)(Mg + (size_t)r0 * Sn + q0 + col) = p0;
            *(float2*)(Mg + (size_t)r1 * Sn + q0 + col) = p1;
            Pr[j][0] = f2tf(p0.x); Pr[j][1] = f2tf(p0.y);
            Pr[j][2] = f2tf(p1.x); Pr[j][3] = f2tf(p1.y);
            rj *= g8i;
        }
        // intra over this 64-key half
        #pragma unroll
        for (int kk = 0; kk < 8; kk++) {
            unsigned c0A = __shfl_sync(0xffffffffu, Pr[kk][0], srcA);
            unsigned c1A = __shfl_sync(0xffffffffu, Pr[kk][1], srcA);
            unsigned c2A = __shfl_sync(0xffffffffu, Pr[kk][2], srcA);
            unsigned c3A = __shfl_sync(0xffffffffu, Pr[kk][3], srcA);
            unsigned c0B = __shfl_sync(0xffffffffu, Pr[kk][0], srcB);
            unsigned c1B = __shfl_sync(0xffffffffu, Pr[kk][1], srcB);
            unsigned c2B = __shfl_sync(0xffffffffu, Pr[kk][2], srcB);
            unsigned c3B = __shfl_sync(0xffffffffu, Pr[kk][3], srcB);
            const bool odd = (tg & 1);
            unsigned a0 = odd ? c1A : c0A;
            unsigned a1 = odd ? c3A : c2A;
            unsigned a2 = odd ? c1B : c0B;
            unsigned a3 = odd ? c3B : c2B;
            const float* v0 = Vd + (jh * 64 + kk * 8 + tg) * KS_STRIDE;
            const float* v1 = Vd + (jh * 64 + kk * 8 + tg + 4) * KS_STRIDE;
            uint4 bA0 = *(const uint4*)(v0 + gr * 4);
            uint4 bB0 = *(const uint4*)(v1 + gr * 4);
            uint4 bA1 = *(const uint4*)(v0 + 32 + gr * 4);
            uint4 bB1 = *(const uint4*)(v1 + 32 + gr * 4);
            mma_tf32(Oa[0], a0, a1, a2, a3, bA0.x, bB0.x);
            mma_tf32(Oa[1], a0, a1, a2, a3, bA0.y, bB0.y);
            mma_tf32(Oa[2], a0, a1, a2, a3, bA0.z, bB0.z);
            mma_tf32(Oa[3], a0, a1, a2, a3, bA0.w, bB0.w);
            mma_tf32(Oa[4], a0, a1, a2, a3, bA1.x, bB1.x);
            mma_tf32(Oa[5], a0, a1, a2, a3, bA1.y, bB1.y);
            mma_tf32(Oa[6], a0, a1, a2, a3, bA1.z, bB1.z);
            mma_tf32(Oa[7], a0, a1, a2, a3, bA1.w, bB1.w);
        }
    }

    // inter: Q(regs) @ State(hi/lo tf32), scaled by gamma^(local row)
    {
        float OaI[8][4];
        #pragma unroll
        for (int j = 0; j < 8; j++)
            #pragma unroll
            for (int i = 0; i < 4; i++) OaI[j][i] = 0.f;
        #pragma unroll
        for (int kk = 0; kk < 8; kk++) {
            #pragma unroll
            for (int j = 0; j < 8; j++) {
                const int colb = j * 8 + gr;
                float bv0 = Sts[(kk * 8 + tg) * ST_STRIDE + colb];
                float bv1 = Sts[(kk * 8 + tg + 4) * ST_STRIDE + colb];
                unsigned b0h = f2tf(bv0), b1h = f2tf(bv1);
                unsigned b0l = f2tf(bv0 - __uint_as_float(b0h));
                unsigned b1l = f2tf(bv1 - __uint_as_float(b1h));
                mma_tf32(OaI[j], qA[kk].x, qB[kk].x, qA[kk].y, qB[kk].y, b0h, b1h);
                mma_tf32(OaI[j], qA[kk].x, qB[kk].x, qA[kk].y, qB[kk].y, b0l, b1l);
            }
        }
        const float s0 = exp2f((float)(row0 + gr) * l2g);
        const float s1 = exp2f((float)(row0 + gr + 8) * l2g);
        #pragma unroll
        for (int j = 0; j < 8; j++) {
            Oa[j][0] += s0 * OaI[j][0]; Oa[j][1] += s0 * OaI[j][1];
            Oa[j][2] += s1 * OaI[j][2]; Oa[j][3] += s1 * OaI[j][3];
        }
    }

    // write O
    #pragma unroll
    for (int j = 0; j < 8; j++) {
        const int c = j * 8 + tg * 2;
        *(float2*)(Og + (size_t)r0 * DHn + c) = make_float2(Oa[j][0], Oa[j][1]);
        *(float2*)(Og + (size_t)r1 * DHn + c) = make_float2(Oa[j][2], Oa[j][3]);
    }

    // zero-fill masked MSR tiles (cols >= (qblk+1)*128)
    {
        const int c0z = (qblk + 1) * BN;
        if (c0z < Sn) {
            const int nf4 = (Sn - c0z) >> 2;
            const float4 z = make_float4(0.f, 0.f, 0.f, 0.f);
            for (int r = warp; r < BM; r += 8) {
                float* row = Mg + (size_t)r * Sn + c0z;
                for (int t = lane; t < nf4; t += 32)
                    *(float4*)(row + t * 4) = z;
            }
        }
    }
}

extern "C" void kernel_launch(void* const* d_in, const int* in_sizes, int n_in,
                              void* d_out, int out_size) {
    const float* Q = (const float*)d_in[0];
    const float* K = (const float*)d_in[1];
    const float* V = (const float*)d_in[2];
    // d_in[3] = D  (computed analytically in-kernel)

    float* out = (float*)d_out;                                  // [B,H,S,DH]
    float* msr = out + (size_t)Bsz * Hn * Sn * DHn;              // [B,H,S,S]

    const size_t smemA = (size_t)(2 * BN * 72) * sizeof(float);
    cudaFuncSetAttribute(state_tiles_kernel,
                         cudaFuncAttributeMaxDynamicSharedMemorySize, (int)smemA);
    const size_t smemC1 = (size_t)(2 * BM * KS_STRIDE) * sizeof(float);
    cudaFuncSetAttribute(msr_stream_kernel,
                         cudaFuncAttributeMaxDynamicSharedMemorySize, (int)smemC1);
    const size_t smemC2 = (size_t)(3 * BM * KS_STRIDE + DHn * ST_STRIDE) * sizeof(float);
    cudaFuncSetAttribute(retnet_tail_kernel,
                         cudaFuncAttributeMaxDynamicSharedMemorySize, (int)smemC2);

    state_tiles_kernel<<<dim3(NT, Bsz * Hn), 256, smemA>>>(K, V);
    retnet_tail_kernel<<<dim3(NT, Bsz * Hn), 256, smemC2>>>(Q, K, V, out, msr);
    msr_stream_kernel<<<dim3(15, Bsz * Hn), 256, smemC1>>>(Q, K, msr);
}

// round 13
// speedup vs baseline: 1.1414x; 1.1414x over previous
#include <cuda_runtime.h>
#include <cstdint>
#include <math.h>

// RetNet retention, chunked-state form (R9 backbone). R13: per-tile barrier moved
// to right after K staging, so the decay+MSR store drain overlaps other warps'
// next-tile gemm1 (inter-warp drift). Everything else identical to R9.
#define Bsz 2
#define Hn 16
#define Sn 2048
#define DHn 64
#define BM 128
#define BN 128
#define NT 16
#define THREADS 512
#define KS_STRIDE 72
#define ST_STRIDE 72
#define OS_STRIDE 66

__device__ float g_T[(size_t)Bsz * Hn * NT * DHn * DHn];   // 8 MB scratch

__device__ __forceinline__ unsigned f2tf(float f) {
    unsigned r; asm("cvt.rna.tf32.f32 %0, %1;" : "=r"(r) : "f"(f)); return r;
}

__device__ __forceinline__ void mma_tf32(float c[4], unsigned a0, unsigned a1,
                                         unsigned a2, unsigned a3, unsigned b0, unsigned b1) {
    asm volatile("mma.sync.aligned.m16n8k8.row.col.f32.tf32.tf32.f32 "
                 "{%0,%1,%2,%3}, {%4,%5,%6,%7}, {%8,%9}, {%0,%1,%2,%3};\n"
                 : "+f"(c[0]), "+f"(c[1]), "+f"(c[2]), "+f"(c[3])
                 : "r"(a0), "r"(a1), "r"(a2), "r"(a3), "r"(b0), "r"(b1));
}

// ---------------- kernel A: T[j] = sum_m gamma^(128-m_loc) K[m] (x) V[m] ----------------
__global__ __launch_bounds__(256, 1)
void state_tiles_kernel(const float* __restrict__ K, const float* __restrict__ V) {
    extern __shared__ float smemA[];
    float* Ks = smemA;
    float* Vs = Ks + BN * 72;
    const int tid = threadIdx.x, warp = tid >> 5, lane = tid & 31;
    const int gr = lane >> 2, tg = lane & 3;
    const int rowA = (warp & 3) * 16, n0 = (warp >> 2) * 32;
    const int jt = blockIdx.x, bh = blockIdx.y, h = bh % Hn, k0 = jt * BN;
    const double epsd = ldexp(1.0, -5 - h);
    const float l2g = (float)(log1p(-epsd) * 1.4426950408889634);
    const float* Kg = K + ((size_t)bh * Sn + k0) * DHn;
    const float* Vg = V + ((size_t)bh * Sn + k0) * DHn;

    for (int i = 0; i < 8; i++) {
        const int idx = tid + i * 256, r = idx >> 4, c = (idx & 15) << 2;
        const float w = exp2f((float)(128 - r) * l2g);
        float4 kv = *(const float4*)(Kg + (size_t)r * DHn + c);
        unsigned* kd = (unsigned*)(Ks + r * 72 + c);
        kd[0] = f2tf(w * kv.x); kd[1] = f2tf(w * kv.y);
        kd[2] = f2tf(w * kv.z); kd[3] = f2tf(w * kv.w);
        float4 vv = *(const float4*)(Vg + (size_t)r * DHn + c);
        unsigned* vd = (unsigned*)(Vs + r * 72 + c);
        vd[0] = f2tf(vv.x); vd[1] = f2tf(vv.y); vd[2] = f2tf(vv.z); vd[3] = f2tf(vv.w);
    }
    __syncthreads();

    float acc[4][4];
    #pragma unroll
    for (int j = 0; j < 4; j++)
        #pragma unroll
        for (int i = 0; i < 4; i++) acc[j][i] = 0.f;
    const unsigned* k32 = (const unsigned*)Ks;
    const unsigned* v32 = (const unsigned*)Vs;
    #pragma unroll
    for (int kk = 0; kk < 16; kk++) {
        const int m = kk * 8 + tg;
        unsigned a0 = k32[m * 72 + rowA + gr],       a1 = k32[m * 72 + rowA + gr + 8];
        unsigned a2 = k32[(m + 4) * 72 + rowA + gr], a3 = k32[(m + 4) * 72 + rowA + gr + 8];
        #pragma unroll
        for (int j = 0; j < 4; j++) {
            unsigned b0 = v32[m * 72 + n0 + j * 8 + gr];
            unsigned b1 = v32[(m + 4) * 72 + n0 + j * 8 + gr];
            mma_tf32(acc[j], a0, a1, a2, a3, b0, b1);
        }
    }
    float* T = g_T + (((size_t)bh * NT + jt) * DHn) * DHn;
    #pragma unroll
    for (int j = 0; j < 4; j++) {
        const int col = n0 + j * 8 + tg * 2;
        *(float2*)(T + (rowA + gr) * DHn + col)     = make_float2(acc[j][0], acc[j][1]);
        *(float2*)(T + (rowA + gr + 8) * DHn + col) = make_float2(acc[j][2], acc[j][3]);
    }
}

// ---------------- kernel C: MSR + out ----------------
__global__ __launch_bounds__(THREADS, 1)
void retnet_msr_kernel(const float* __restrict__ Q, const float* __restrict__ K,
                       const float* __restrict__ V,
                       float* __restrict__ Out, float* __restrict__ MSR) {
    extern __shared__ float smem[];
    float* Ks0 = smem;                 // [128][72] K buffer 0 (octet-perm)
    float* Ks1 = smem + 9216;          // [128][72] K buffer 1 / Q stage / diag V
    float* Sts = smem + 18432;         // [64][72] State fp32
    float* Os  = smem;                 // O-reduction scratch (overlay, post-loop)

    const int tid = threadIdx.x, warp = tid >> 5, lane = tid & 31;
    const int gr = lane >> 2, tg = lane & 3;
    const int wm = warp >> 1, wn = warp & 1;
    const int row0 = wm * 16, n0g1 = wn * 64, n0g2 = wn * 32;

    const int qblk = 15 - blockIdx.x;  // heavy tiles first
    const int bh = blockIdx.y, h = bh % Hn, q0 = qblk * BM;

    const float* Qg = Q + ((size_t)bh * Sn + q0) * DHn;
    const float* Kg = K + (size_t)bh * Sn * DHn;
    const float* Vg = V + (size_t)bh * Sn * DHn;
    float* Og = Out + ((size_t)bh * Sn + q0) * DHn;
    float* Mg = MSR + ((size_t)bh * Sn + q0) * Sn;

    const double epsd = ldexp(1.0, -5 - h);
    const float l2g = (float)(log1p(-epsd) * 1.4426950408889634);
    const float pr0 = exp2f((float)(q0 + row0 + gr) * l2g);
    const float pr1 = exp2f((float)(q0 + row0 + gr + 8) * l2g);
    const float g1i = exp2f(-l2g);
    const float g8i = exp2f(-8.0f * l2g);

    const int lr = tid >> 4, c0 = (tid & 15) << 2;
    const int pbase = (c0 & ~7) | ((c0 >> 2) & 1);
    const int vc0 = ((c0 & 7) * 4) + ((c0 & 31) >> 3) + (c0 & ~31);

    // ---- prologue: stage Q->Ks1, K0->Ks0 (perm); combine State -> Sts ----
    #pragma unroll
    for (int i = 0; i < 4; i++) {
        const int r = lr + i * 32;
        float4 qv = *(const float4*)(Qg + (size_t)r * DHn + c0);
        unsigned* qd = (unsigned*)(Ks1 + r * KS_STRIDE + pbase);
        qd[0] = f2tf(qv.x); qd[2] = f2tf(qv.y); qd[4] = f2tf(qv.z); qd[6] = f2tf(qv.w);
        float4 kv = *(const float4*)(Kg + (size_t)r * DHn + c0);
        unsigned* kd = (unsigned*)(Ks0 + r * KS_STRIDE + pbase);
        kd[0] = f2tf(kv.x); kd[2] = f2tf(kv.y); kd[4] = f2tf(kv.z); kd[6] = f2tf(kv.w);
    }
    {
        const int sdp = tid >> 3, sdc = (tid & 7) << 3;
        float sa[8];
        #pragma unroll
        for (int i = 0; i < 8; i++) sa[i] = 0.f;
        for (int j = 0; j < qblk; j++) {
            const float w = exp2f(128.0f * (float)(qblk - 1 - j) * l2g);
            const float4* tp =
                (const float4*)(g_T + (((size_t)bh * NT + j) * DHn + sdp) * DHn + sdc);
            float4 ta = tp[0], tb = tp[1];
            sa[0] += w * ta.x; sa[1] += w * ta.y; sa[2] += w * ta.z; sa[3] += w * ta.w;
            sa[4] += w * tb.x; sa[5] += w * tb.y; sa[6] += w * tb.z; sa[7] += w * tb.w;
        }
        *(float4*)(Sts + sdp * ST_STRIDE + sdc)     = make_float4(sa[0], sa[1], sa[2], sa[3]);
        *(float4*)(Sts + sdp * ST_STRIDE + sdc + 4) = make_float4(sa[4], sa[5], sa[6], sa[7]);
    }
    __syncthreads();

    // ---- hoist Q A-fragments into registers (whole-kernel lifetime) ----
    uint2 qA[8], qB[8];
    #pragma unroll
    for (int kk = 0; kk < 8; kk++) {
        const int fc = kk * 8 + tg * 2;
        qA[kk] = *(const uint2*)(Ks1 + (row0 + gr) * KS_STRIDE + fc);
        qB[kk] = *(const uint2*)(Ks1 + (row0 + gr + 8) * KS_STRIDE + fc);
    }
    __syncthreads();   // Ks1 free for K prefetch reuse

    // ---- off-diagonal key-tile loop ----
    // Order per iter: LDG K(kt+1) | gemm1(kt) | STS K(kt+1) | BARRIER | decay+MSR(kt).
    // After the barrier B_kt is dead and B_(kt+1) complete, so the store drain
    // overlaps other warps' next-tile gemm1.
    for (int kt = 0; kt < qblk; kt++) {
        float* Ksb = (kt & 1) ? Ks1 : Ks0;
        float* Ksn = (kt & 1) ? Ks0 : Ks1;
        const int k0 = kt * BN;

        // prefetch next K (tile kt+1; on last iter this is the diag tile)
        float4 kp[4];
        const float* kg = Kg + (size_t)(k0 + BN) * DHn;
        #pragma unroll
        for (int i = 0; i < 4; i++)
            kp[i] = *(const float4*)(kg + (size_t)(lr + i * 32) * DHn + c0);

        // gemm1: S[16 x 64 per warp] = Q @ K^T (A from regs)
        float Sa[8][4];
        #pragma unroll
        for (int j = 0; j < 8; j++)
            #pragma unroll
            for (int i = 0; i < 4; i++) Sa[j][i] = 0.f;
        #pragma unroll
        for (int kk = 0; kk < 8; kk++) {
            const int fc = kk * 8 + tg * 2;
            #pragma unroll
            for (int j = 0; j < 8; j++) {
                uint2 b = *(const uint2*)(Ksb + (n0g1 + j * 8 + gr) * KS_STRIDE + fc);
                mma_tf32(Sa[j], qA[kk].x, qB[kk].x, qA[kk].y, qB[kk].y, b.x, b.y);
            }
        }

        // store prefetched K, then barrier
        #pragma unroll
        for (int i = 0; i < 4; i++) {
            unsigned* kd = (unsigned*)(Ksn + (lr + i * 32) * KS_STRIDE + pbase);
            kd[0] = f2tf(kp[i].x); kd[2] = f2tf(kp[i].y);
            kd[4] = f2tf(kp[i].z); kd[6] = f2tf(kp[i].w);
        }
        __syncthreads();

        // decay + MSR store (after barrier: overlaps next-tile work of other warps)
        {
            float* mg = Mg + k0;
            const int r0 = row0 + gr, r1 = r0 + 8;
            float rj = exp2f(-(float)(k0 + n0g1 + tg * 2) * l2g);
            #pragma unroll
            for (int j = 0; j < 8; j++) {
                const int col = n0g1 + j * 8 + tg * 2;
                const float dx = rj, dy = rj * g1i;
                float2 p0 = make_float2(Sa[j][0] * (pr0 * dx), Sa[j][1] * (pr0 * dy));
                float2 p1 = make_float2(Sa[j][2] * (pr1 * dx), Sa[j][3] * (pr1 * dy));
                *(float2*)(mg + (size_t)r0 * Sn + col) = p0;
                *(float2*)(mg + (size_t)r1 * Sn + col) = p1;
                rj *= g8i;
            }
        }
    }

    // ---- diagonal tile ----
    const int k0d = qblk * BN;
    float* Kdiag = (qblk & 1) ? Ks1 : Ks0;
    float* Vbuf  = (qblk & 1) ? Ks0 : Ks1;
    // Kdiag was staged before the last barrier (or prologue if qblk==0).
    // Vbuf died at the last barrier; lagging warps only touch regs/gmem after it.

    // load+stage diag V into dead buffer (32-group interleave for LDS.128 B-frags)
    #pragma unroll
    for (int i = 0; i < 4; i++) {
        const int r = lr + i * 32;
        float4 vv = *(const float4*)(Vg + (size_t)(q0 + r) * DHn + c0);
        unsigned* vd = (unsigned*)(Vbuf + r * KS_STRIDE + vc0);
        vd[0] = f2tf(vv.x); vd[4] = f2tf(vv.y); vd[8] = f2tf(vv.z); vd[12] = f2tf(vv.w);
    }

    // gemm1 diag
    float Sa[8][4];
    #pragma unroll
    for (int j = 0; j < 8; j++)
        #pragma unroll
        for (int i = 0; i < 4; i++) Sa[j][i] = 0.f;
    #pragma unroll
    for (int kk = 0; kk < 8; kk++) {
        const int fc = kk * 8 + tg * 2;
        #pragma unroll
        for (int j = 0; j < 8; j++) {
            uint2 b = *(const uint2*)(Kdiag + (n0g1 + j * 8 + gr) * KS_STRIDE + fc);
            mma_tf32(Sa[j], qA[kk].x, qB[kk].x, qA[kk].y, qB[kk].y, b.x, b.y);
        }
    }
    __syncthreads();   // V staged by all warps

    // masked decay -> MSR + Pr regs
    unsigned Pr[8][4];
    {
        float* mg = Mg + k0d;
        const int r0 = row0 + gr, r1 = r0 + 8;
        float rj = exp2f(-(float)(k0d + n0g1 + tg * 2) * l2g);
        #pragma unroll
        for (int j = 0; j < 8; j++) {
            const int col = n0g1 + j * 8 + tg * 2;
            const float dx = rj, dy = rj * g1i;
            float d00 = pr0 * dx, d01 = pr0 * dy;
            float d10 = pr1 * dx, d11 = pr1 * dy;
            const int m0 = k0d + col;
            const int nr0 = q0 + r0, nr1 = q0 + r1;
            if (nr0 < m0)     d00 = 0.f;
            if (nr0 < m0 + 1) d01 = 0.f;
            if (nr1 < m0)     d10 = 0.f;
            if (nr1 < m0 + 1) d11 = 0.f;
            float2 p0 = make_float2(Sa[j][0] * d00, Sa[j][1] * d01);
            float2 p1 = make_float2(Sa[j][2] * d10, Sa[j][3] * d11);
            *(float2*)(mg + (size_t)r0 * Sn + col) = p0;
            *(float2*)(mg + (size_t)r1 * Sn + col) = p1;
            Pr[j][0] = f2tf(p0.x); Pr[j][1] = f2tf(p0.y);
            Pr[j][2] = f2tf(p1.x); Pr[j][3] = f2tf(p1.y);
            rj *= g8i;
        }
    }

    // intra: O[16 x 64] += P(own 64 keys) @ V, A-frags via shfl
    float Oa[8][4];
    #pragma unroll
    for (int j = 0; j < 8; j++)
        #pragma unroll
        for (int i = 0; i < 4; i++) Oa[j][i] = 0.f;
    const int srcA = (lane & ~3) | (tg >> 1);
    const int srcB = srcA + 2;
    #pragma unroll
    for (int kk = 0; kk < 8; kk++) {
        unsigned c0A = __shfl_sync(0xffffffffu, Pr[kk][0], srcA);
        unsigned c1A = __shfl_sync(0xffffffffu, Pr[kk][1], srcA);
        unsigned c2A = __shfl_sync(0xffffffffu, Pr[kk][2], srcA);
        unsigned c3A = __shfl_sync(0xffffffffu, Pr[kk][3], srcA);
        unsigned c0B = __shfl_sync(0xffffffffu, Pr[kk][0], srcB);
        unsigned c1B = __shfl_sync(0xffffffffu, Pr[kk][1], srcB);
        unsigned c2B = __shfl_sync(0xffffffffu, Pr[kk][2], srcB);
        unsigned c3B = __shfl_sync(0xffffffffu, Pr[kk][3], srcB);
        const bool odd = (tg & 1);
        unsigned a0 = odd ? c1A : c0A;
        unsigned a1 = odd ? c3A : c2A;
        unsigned a2 = odd ? c1B : c0B;
        unsigned a3 = odd ? c3B : c2B;
        const float* v0 = Vbuf + (n0g1 + kk * 8 + tg) * KS_STRIDE;
        const float* v1 = Vbuf + (n0g1 + kk * 8 + tg + 4) * KS_STRIDE;
        uint4 bA0 = *(const uint4*)(v0 + gr * 4);
        uint4 bB0 = *(const uint4*)(v1 + gr * 4);
        uint4 bA1 = *(const uint4*)(v0 + 32 + gr * 4);
        uint4 bB1 = *(const uint4*)(v1 + 32 + gr * 4);
        mma_tf32(Oa[0], a0, a1, a2, a3, bA0.x, bB0.x);
        mma_tf32(Oa[1], a0, a1, a2, a3, bA0.y, bB0.y);
        mma_tf32(Oa[2], a0, a1, a2, a3, bA0.z, bB0.z);
        mma_tf32(Oa[3], a0, a1, a2, a3, bA0.w, bB0.w);
        mma_tf32(Oa[4], a0, a1, a2, a3, bA1.x, bB1.x);
        mma_tf32(Oa[5], a0, a1, a2, a3, bA1.y, bB1.y);
        mma_tf32(Oa[6], a0, a1, a2, a3, bA1.z, bB1.z);
        mma_tf32(Oa[7], a0, a1, a2, a3, bA1.w, bB1.w);
    }

    // inter: Q(regs) @ State(hi/lo tf32), scaled by gamma^(local row)
    {
        float OaI[4][4];
        #pragma unroll
        for (int j = 0; j < 4; j++)
            #pragma unroll
            for (int i = 0; i < 4; i++) OaI[j][i] = 0.f;
        #pragma unroll
        for (int kk = 0; kk < 8; kk++) {
            #pragma unroll
            for (int j = 0; j < 4; j++) {
                const int colb = n0g2 + j * 8 + gr;
                float bv0 = Sts[(kk * 8 + tg) * ST_STRIDE + colb];
                float bv1 = Sts[(kk * 8 + tg + 4) * ST_STRIDE + colb];
                unsigned b0h = f2tf(bv0), b1h = f2tf(bv1);
                unsigned b0l = f2tf(bv0 - __uint_as_float(b0h));
                unsigned b1l = f2tf(bv1 - __uint_as_float(b1h));
                mma_tf32(OaI[j], qA[kk].x, qB[kk].x, qA[kk].y, qB[kk].y, b0h, b1h);
                mma_tf32(OaI[j], qA[kk].x, qB[kk].x, qA[kk].y, qB[kk].y, b0l, b1l);
            }
        }
        const float s0 = exp2f((float)(row0 + gr) * l2g);
        const float s1 = exp2f((float)(row0 + gr + 8) * l2g);
        const int jo = wn * 4;
        #pragma unroll
        for (int j = 0; j < 4; j++) {
            Oa[jo + j][0] += s0 * OaI[j][0]; Oa[jo + j][1] += s0 * OaI[j][1];
            Oa[jo + j][2] += s1 * OaI[j][2]; Oa[jo + j][3] += s1 * OaI[j][3];
        }
    }
    __syncthreads();   // K/V buffers dead -> Os overlay safe

    // pair-reduce across wn, write O
    if (wn == 1) {
        #pragma unroll
        for (int j = 0; j < 8; j++) {
            const int c = j * 8 + tg * 2;
            *(float2*)&Os[(row0 + gr) * OS_STRIDE + c]     = make_float2(Oa[j][0], Oa[j][1]);
            *(float2*)&Os[(row0 + gr + 8) * OS_STRIDE + c] = make_float2(Oa[j][2], Oa[j][3]);
        }
    }
    __syncthreads();
    if (wn == 0) {
        #pragma unroll
        for (int j = 0; j < 8; j++) {
            const int c = j * 8 + tg * 2;
            float2 o0 = *(const float2*)&Os[(row0 + gr) * OS_STRIDE + c];
            float2 o1 = *(const float2*)&Os[(row0 + gr + 8) * OS_STRIDE + c];
            *(float2*)(Og + (size_t)(row0 + gr) * DHn + c) =
                make_float2(Oa[j][0] + o0.x, Oa[j][1] + o0.y);
            *(float2*)(Og + (size_t)(row0 + gr + 8) * DHn + c) =
                make_float2(Oa[j][2] + o1.x, Oa[j][3] + o1.y);
        }
    }

    // zero-fill masked MSR tiles (div-free: warp per row, lane over cols)
    {
        const int nzt = 15 - qblk;
        if (nzt > 0) {
            const int c0z = (qblk + 1) * BN;
            const float4 z = make_float4(0.f, 0.f, 0.f, 0.f);
            const int nf4 = nzt * 32;
            for (int r = warp; r < BM; r += 16) {
                float* row = Mg + (size_t)r * Sn + c0z;
                for (int t = lane; t < nf4; t += 32)
                    *(float4*)(row + t * 4) = z;
            }
        }
    }
}

extern "C" void kernel_launch(void* const* d_in, const int* in_sizes, int n_in,
                              void* d_out, int out_size) {
    const float* Q = (const float*)d_in[0];
    const float* K = (const float*)d_in[1];
    const float* V = (const float*)d_in[2];
    // d_in[3] = D  (computed analytically in-kernel)

    float* out = (float*)d_out;                                  // [B,H,S,DH]
    float* msr = out + (size_t)Bsz * Hn * Sn * DHn;              // [B,H,S,S]

    const size_t smemA = (size_t)(2 * BN * 72) * sizeof(float);
    cudaFuncSetAttribute(state_tiles_kernel,
                         cudaFuncAttributeMaxDynamicSharedMemorySize, (int)smemA);
    const size_t smemC = (size_t)(2 * BM * KS_STRIDE + DHn * ST_STRIDE) * sizeof(float);
    cudaFuncSetAttribute(retnet_msr_kernel,
                         cudaFuncAttributeMaxDynamicSharedMemorySize, (int)smemC);

    state_tiles_kernel<<<dim3(NT, Bsz * Hn), 256, smemA>>>(K, V);
    retnet_msr_kernel<<<dim3(Sn / BM, Bsz * Hn), THREADS, smemC>>>(Q, K, V, out, msr);
}

// round 15
// speedup vs baseline: 1.2214x; 1.0701x over previous
#include <cuda_runtime.h>
#include <cstdint>
#include <math.h>

// RetNet retention, chunked-state form (R9 semantics). R14: 256-thr CTAs, 2/SM,
// BM=128 kept (same traffic as R9); warp owns 16 rows x 128 keys in two halves;
// independent per-CTA barriers overlap phases across co-resident CTAs.
#define Bsz 2
#define Hn 16
#define Sn 2048
#define DHn 64
#define BM 128
#define BN 128
#define NT 16
#define THREADS 256
#define KS_STRIDE 72
#define ST_STRIDE 72

__device__ float g_T[(size_t)Bsz * Hn * NT * DHn * DHn];   // 8 MB scratch

__device__ __forceinline__ unsigned f2tf(float f) {
    unsigned r; asm("cvt.rna.tf32.f32 %0, %1;" : "=r"(r) : "f"(f)); return r;
}

__device__ __forceinline__ void mma_tf32(float c[4], unsigned a0, unsigned a1,
                                         unsigned a2, unsigned a3, unsigned b0, unsigned b1) {
    asm volatile("mma.sync.aligned.m16n8k8.row.col.f32.tf32.tf32.f32 "
                 "{%0,%1,%2,%3}, {%4,%5,%6,%7}, {%8,%9}, {%0,%1,%2,%3};\n"
                 : "+f"(c[0]), "+f"(c[1]), "+f"(c[2]), "+f"(c[3])
                 : "r"(a0), "r"(a1), "r"(a2), "r"(a3), "r"(b0), "r"(b1));
}

// ---------------- kernel A: T[j] = sum_m gamma^(128-m_loc) K[m] (x) V[m] ----------------
__global__ __launch_bounds__(256, 1)
void state_tiles_kernel(const float* __restrict__ K, const float* __restrict__ V) {
    extern __shared__ float smemA[];
    float* Ks = smemA;
    float* Vs = Ks + BN * 72;
    const int tid = threadIdx.x, warp = tid >> 5, lane = tid & 31;
    const int gr = lane >> 2, tg = lane & 3;
    const int rowA = (warp & 3) * 16, n0 = (warp >> 2) * 32;
    const int jt = blockIdx.x, bh = blockIdx.y, h = bh % Hn, k0 = jt * BN;
    const double epsd = ldexp(1.0, -5 - h);
    const float l2g = (float)(log1p(-epsd) * 1.4426950408889634);
    const float* Kg = K + ((size_t)bh * Sn + k0) * DHn;
    const float* Vg = V + ((size_t)bh * Sn + k0) * DHn;

    for (int i = 0; i < 8; i++) {
        const int idx = tid + i * 256, r = idx >> 4, c = (idx & 15) << 2;
        const float w = exp2f((float)(128 - r) * l2g);
        float4 kv = *(const float4*)(Kg + (size_t)r * DHn + c);
        unsigned* kd = (unsigned*)(Ks + r * 72 + c);
        kd[0] = f2tf(w * kv.x); kd[1] = f2tf(w * kv.y);
        kd[2] = f2tf(w * kv.z); kd[3] = f2tf(w * kv.w);
        float4 vv = *(const float4*)(Vg + (size_t)r * DHn + c);
        unsigned* vd = (unsigned*)(Vs + r * 72 + c);
        vd[0] = f2tf(vv.x); vd[1] = f2tf(vv.y); vd[2] = f2tf(vv.z); vd[3] = f2tf(vv.w);
    }
    __syncthreads();

    float acc[4][4];
    #pragma unroll
    for (int j = 0; j < 4; j++)
        #pragma unroll
        for (int i = 0; i < 4; i++) acc[j][i] = 0.f;
    const unsigned* k32 = (const unsigned*)Ks;
    const unsigned* v32 = (const unsigned*)Vs;
    #pragma unroll
    for (int kk = 0; kk < 16; kk++) {
        const int m = kk * 8 + tg;
        unsigned a0 = k32[m * 72 + rowA + gr],       a1 = k32[m * 72 + rowA + gr + 8];
        unsigned a2 = k32[(m + 4) * 72 + rowA + gr], a3 = k32[(m + 4) * 72 + rowA + gr + 8];
        #pragma unroll
        for (int j = 0; j < 4; j++) {
            unsigned b0 = v32[m * 72 + n0 + j * 8 + gr];
            unsigned b1 = v32[(m + 4) * 72 + n0 + j * 8 + gr];
            mma_tf32(acc[j], a0, a1, a2, a3, b0, b1);
        }
    }
    float* T = g_T + (((size_t)bh * NT + jt) * DHn) * DHn;
    #pragma unroll
    for (int j = 0; j < 4; j++) {
        const int col = n0 + j * 8 + tg * 2;
        *(float2*)(T + (rowA + gr) * DHn + col)     = make_float2(acc[j][0], acc[j][1]);
        *(float2*)(T + (rowA + gr + 8) * DHn + col) = make_float2(acc[j][2], acc[j][3]);
    }
}

// ---------------- kernel C: MSR + out; 256 thr, 2 CTAs/SM ----------------
__global__ __launch_bounds__(THREADS, 2)
void retnet_msr_kernel(const float* __restrict__ Q, const float* __restrict__ K,
                       const float* __restrict__ V,
                       float* __restrict__ Out, float* __restrict__ MSR) {
    extern __shared__ float smem[];
    float* Ks0 = smem;                 // [128][72] K buffer 0 (octet-perm)
    float* Ks1 = smem + 9216;          // [128][72] K buffer 1 / Q stage / diag V
    float* Sts = smem + 18432;         // [64][72] State fp32

    const int tid = threadIdx.x, warp = tid >> 5, lane = tid & 31;
    const int gr = lane >> 2, tg = lane & 3;
    const int row0 = warp * 16;        // 8 warps cover 128 q-rows

    const int qblk = 15 - blockIdx.x;  // heavy tiles first
    const int bh = blockIdx.y, h = bh % Hn, q0 = qblk * BM;

    const float* Qg = Q + ((size_t)bh * Sn + q0) * DHn;
    const float* Kg = K + (size_t)bh * Sn * DHn;
    const float* Vg = V + (size_t)bh * Sn * DHn;
    float* Og = Out + ((size_t)bh * Sn + q0) * DHn;
    float* Mg = MSR + ((size_t)bh * Sn + q0) * Sn;

    const double epsd = ldexp(1.0, -5 - h);
    const float l2g = (float)(log1p(-epsd) * 1.4426950408889634);
    const float pr0 = exp2f((float)(q0 + row0 + gr) * l2g);
    const float pr1 = exp2f((float)(q0 + row0 + gr + 8) * l2g);
    const float g1i = exp2f(-l2g);
    const float g8i = exp2f(-8.0f * l2g);

    const int lr = tid >> 4, c0 = (tid & 15) << 2;   // 16 rows per step
    const int pbase = (c0 & ~7) | ((c0 >> 2) & 1);
    const int vc0 = ((c0 & 7) * 4) + ((c0 & 31) >> 3) + (c0 & ~31);

    // ---- prologue: stage Q->Ks1, K0->Ks0 (perm); combine State -> Sts ----
    #pragma unroll
    for (int i = 0; i < 8; i++) {
        const int r = lr + i * 16;
        float4 qv = *(const float4*)(Qg + (size_t)r * DHn + c0);
        unsigned* qd = (unsigned*)(Ks1 + r * KS_STRIDE + pbase);
        qd[0] = f2tf(qv.x); qd[2] = f2tf(qv.y); qd[4] = f2tf(qv.z); qd[6] = f2tf(qv.w);
        float4 kv = *(const float4*)(Kg + (size_t)r * DHn + c0);
        unsigned* kd = (unsigned*)(Ks0 + r * KS_STRIDE + pbase);
        kd[0] = f2tf(kv.x); kd[2] = f2tf(kv.y); kd[4] = f2tf(kv.z); kd[6] = f2tf(kv.w);
    }
    {
        const int sdp = tid >> 2, sdc = (tid & 3) << 4;   // 64 rows x 16 floats
        float sa[16];
        #pragma unroll
        for (int i = 0; i < 16; i++) sa[i] = 0.f;
        for (int j = 0; j < qblk; j++) {
            const float w = exp2f(128.0f * (float)(qblk - 1 - j) * l2g);
            const float4* tp =
                (const float4*)(g_T + (((size_t)bh * NT + j) * DHn + sdp) * DHn + sdc);
            #pragma unroll
            for (int t = 0; t < 4; t++) {
                float4 ta = tp[t];
                sa[t*4+0] += w * ta.x; sa[t*4+1] += w * ta.y;
                sa[t*4+2] += w * ta.z; sa[t*4+3] += w * ta.w;
            }
        }
        #pragma unroll
        for (int t = 0; t < 4; t++)
            *(float4*)(Sts + sdp * ST_STRIDE + sdc + t * 4) =
                make_float4(sa[t*4+0], sa[t*4+1], sa[t*4+2], sa[t*4+3]);
    }
    __syncthreads();

    // ---- hoist Q A-fragments (whole-kernel lifetime) ----
    uint2 qA[8], qB[8];
    #pragma unroll
    for (int kk = 0; kk < 8; kk++) {
        const int fc = kk * 8 + tg * 2;
        qA[kk] = *(const uint2*)(Ks1 + (row0 + gr) * KS_STRIDE + fc);
        qB[kk] = *(const uint2*)(Ks1 + (row0 + gr + 8) * KS_STRIDE + fc);
    }
    __syncthreads();   // Ks1 free

    const int r0 = row0 + gr, r1 = r0 + 8;

    // ---- off-diagonal key-tile loop: one barrier per tile ----
    for (int kt = 0; kt < qblk; kt++) {
        const float* Ksb = (kt & 1) ? Ks1 : Ks0;
        float* Ksn = (kt & 1) ? Ks0 : Ks1;
        const int k0 = kt * BN;
        const float* kg = Kg + (size_t)(k0 + BN) * DHn;
        float* mg = Mg + k0;

        // prefetch rows 0..63 of next K tile
        float4 kp[4];
        #pragma unroll
        for (int i = 0; i < 4; i++)
            kp[i] = *(const float4*)(kg + (size_t)(lr + i * 16) * DHn + c0);

        // ---- half A: keys 0..63 ----
        {
            float Sa[8][4];
            #pragma unroll
            for (int j = 0; j < 8; j++)
                #pragma unroll
                for (int i = 0; i < 4; i++) Sa[j][i] = 0.f;
            #pragma unroll
            for (int kk = 0; kk < 8; kk++) {
                const int fc = kk * 8 + tg * 2;
                #pragma unroll
                for (int j = 0; j < 8; j++) {
                    uint2 b = *(const uint2*)(Ksb + (j * 8 + gr) * KS_STRIDE + fc);
                    mma_tf32(Sa[j], qA[kk].x, qB[kk].x, qA[kk].y, qB[kk].y, b.x, b.y);
                }
            }
            float rj = exp2f(-(float)(k0 + tg * 2) * l2g);
            #pragma unroll
            for (int j = 0; j < 8; j++) {
                const int col = j * 8 + tg * 2;
                const float dx = rj, dy = rj * g1i;
                float2 p0 = make_float2(Sa[j][0] * (pr0 * dx), Sa[j][1] * (pr0 * dy));
                float2 p1 = make_float2(Sa[j][2] * (pr1 * dx), Sa[j][3] * (pr1 * dy));
                *(float2*)(mg + (size_t)r0 * Sn + col) = p0;
                *(float2*)(mg + (size_t)r1 * Sn + col) = p1;
                rj *= g8i;
            }
        }

        // stage rows 0..63, prefetch rows 64..127
        #pragma unroll
        for (int i = 0; i < 4; i++) {
            unsigned* kd = (unsigned*)(Ksn + (lr + i * 16) * KS_STRIDE + pbase);
            kd[0] = f2tf(kp[i].x); kd[2] = f2tf(kp[i].y);
            kd[4] = f2tf(kp[i].z); kd[6] = f2tf(kp[i].w);
        }
        #pragma unroll
        for (int i = 0; i < 4; i++)
            kp[i] = *(const float4*)(kg + (size_t)(lr + 64 + i * 16) * DHn + c0);

        // ---- half B: keys 64..127 ----
        {
            float Sa[8][4];
            #pragma unroll
            for (int j = 0; j < 8; j++)
                #pragma unroll
                for (int i = 0; i < 4; i++) Sa[j][i] = 0.f;
            #pragma unroll
            for (int kk = 0; kk < 8; kk++) {
                const int fc = kk * 8 + tg * 2;
                #pragma unroll
                for (int j = 0; j < 8; j++) {
                    uint2 b = *(const uint2*)(Ksb + (64 + j * 8 + gr) * KS_STRIDE + fc);
                    mma_tf32(Sa[j], qA[kk].x, qB[kk].x, qA[kk].y, qB[kk].y, b.x, b.y);
                }
            }
            float rj = exp2f(-(float)(k0 + 64 + tg * 2) * l2g);
            #pragma unroll
            for (int j = 0; j < 8; j++) {
                const int col = 64 + j * 8 + tg * 2;
                const float dx = rj, dy = rj * g1i;
                float2 p0 = make_float2(Sa[j][0] * (pr0 * dx), Sa[j][1] * (pr0 * dy));
                float2 p1 = make_float2(Sa[j][2] * (pr1 * dx), Sa[j][3] * (pr1 * dy));
                *(float2*)(mg + (size_t)r0 * Sn + col) = p0;
                *(float2*)(mg + (size_t)r1 * Sn + col) = p1;
                rj *= g8i;
            }
        }

        // stage rows 64..127
        #pragma unroll
        for (int i = 0; i < 4; i++) {
            unsigned* kd = (unsigned*)(Ksn + (lr + 64 + i * 16) * KS_STRIDE + pbase);
            kd[0] = f2tf(kp[i].x); kd[2] = f2tf(kp[i].y);
            kd[4] = f2tf(kp[i].z); kd[6] = f2tf(kp[i].w);
        }
        __syncthreads();
    }

    // ---- diagonal tile ----
    const int k0d = qblk * BN;
    float* Kdiag = (qblk & 1) ? Ks1 : Ks0;
    float* Vbuf  = (qblk & 1) ? Ks0 : Ks1;

    // stage diag V into dead buffer (32-group interleave)
    #pragma unroll
    for (int i = 0; i < 8; i++) {
        const int r = lr + i * 16;
        float4 vv = *(const float4*)(Vg + (size_t)(q0 + r) * DHn + c0);
        unsigned* vd = (unsigned*)(Vbuf + r * KS_STRIDE + vc0);
        vd[0] = f2tf(vv.x); vd[4] = f2tf(vv.y); vd[8] = f2tf(vv.z); vd[12] = f2tf(vv.w);
    }

    float Oa[8][4];
    #pragma unroll
    for (int j = 0; j < 8; j++)
        #pragma unroll
        for (int i = 0; i < 4; i++) Oa[j][i] = 0.f;
    const int srcA = (lane & ~3) | (tg >> 1);
    const int srcB = srcA + 2;
    bool vsync = false;

    #pragma unroll
    for (int jh = 0; jh < 2; jh++) {
        // gemm1 diag half
        float Sa[8][4];
        #pragma unroll
        for (int j = 0; j < 8; j++)
            #pragma unroll
            for (int i = 0; i < 4; i++) Sa[j][i] = 0.f;
        #pragma unroll
        for (int kk = 0; kk < 8; kk++) {
            const int fc = kk * 8 + tg * 2;
            #pragma unroll
            for (int j = 0; j < 8; j++) {
                uint2 b = *(const uint2*)(Kdiag + (jh * 64 + j * 8 + gr) * KS_STRIDE + fc);
                mma_tf32(Sa[j], qA[kk].x, qB[kk].x, qA[kk].y, qB[kk].y, b.x, b.y);
            }
        }
        if (!vsync) { __syncthreads(); vsync = true; }   // V staged by all warps

        // masked decay -> MSR + Pr
        unsigned Pr[8][4];
        float rj = exp2f(-(float)(k0d + jh * 64 + tg * 2) * l2g);
        #pragma unroll
        for (int j = 0; j < 8; j++) {
            const int col = jh * 64 + j * 8 + tg * 2;
            const float dx = rj, dy = rj * g1i;
            float d00 = pr0 * dx, d01 = pr0 * dy;
            float d10 = pr1 * dx, d11 = pr1 * dy;
            if (r0 < col)     d00 = 0.f;
            if (r0 < col + 1) d01 = 0.f;
            if (r1 < col)     d10 = 0.f;
            if (r1 < col + 1) d11 = 0.f;
            float2 p0 = make_float2(Sa[j][0] * d00, Sa[j][1] * d01);
            float2 p1 = make_float2(Sa[j][2] * d10, Sa[j][3] * d11);
            *(float2*)(Mg + (size_t)r0 * Sn + k0d + col) = p0;
            *(float2*)(Mg + (size_t)r1 * Sn + k0d + col) = p1;
            Pr[j][0] = f2tf(p0.x); Pr[j][1] = f2tf(p0.y);
            Pr[j][2] = f2tf(p1.x); Pr[j][3] = f2tf(p1.y);
            rj *= g8i;
        }

        // intra over this 64-key half (A-frags via shfl)
        #pragma unroll
        for (int kk = 0; kk < 8; kk++) {
            unsigned c0A = __shfl_sync(0xffffffffu, Pr[kk][0], srcA);
            unsigned c1A = __shfl_sync(0xffffffffu, Pr[kk][1], srcA);
            unsigned c2A = __shfl_sync(0xffffffffu, Pr[kk][2], srcA);
            unsigned c3A = __shfl_sync(0xffffffffu, Pr[kk][3], srcA);
            unsigned c0B = __shfl_sync(0xffffffffu, Pr[kk][0], srcB);
            unsigned c1B = __shfl_sync(0xffffffffu, Pr[kk][1], srcB);
            unsigned c2B = __shfl_sync(0xffffffffu, Pr[kk][2], srcB);
            unsigned c3B = __shfl_sync(0xffffffffu, Pr[kk][3], srcB);
            const bool odd = (tg & 1);
            unsigned a0 = odd ? c1A : c0A;
            unsigned a1 = odd ? c3A : c2A;
            unsigned a2 = odd ? c1B : c0B;
            unsigned a3 = odd ? c3B : c2B;
            const float* v0 = Vbuf + (jh * 64 + kk * 8 + tg) * KS_STRIDE;
            const float* v1 = Vbuf + (jh * 64 + kk * 8 + tg + 4) * KS_STRIDE;
            uint4 bA0 = *(const uint4*)(v0 + gr * 4);
            uint4 bB0 = *(const uint4*)(v1 + gr * 4);
            uint4 bA1 = *(const uint4*)(v0 + 32 + gr * 4);
            uint4 bB1 = *(const uint4*)(v1 + 32 + gr * 4);
            mma_tf32(Oa[0], a0, a1, a2, a3, bA0.x, bB0.x);
            mma_tf32(Oa[1], a0, a1, a2, a3, bA0.y, bB0.y);
            mma_tf32(Oa[2], a0, a1, a2, a3, bA0.z, bB0.z);
            mma_tf32(Oa[3], a0, a1, a2, a3, bA0.w, bB0.w);
            mma_tf32(Oa[4], a0, a1, a2, a3, bA1.x, bB1.x);
            mma_tf32(Oa[5], a0, a1, a2, a3, bA1.y, bB1.y);
            mma_tf32(Oa[6], a0, a1, a2, a3, bA1.z, bB1.z);
            mma_tf32(Oa[7], a0, a1, a2, a3, bA1.w, bB1.w);
        }
    }

    // ---- inter: Q(regs) @ State(hi/lo tf32), scaled by gamma^(local row) ----
    {
        float OaI[8][4];
        #pragma unroll
        for (int j = 0; j < 8; j++)
            #pragma unroll
            for (int i = 0; i < 4; i++) OaI[j][i] = 0.f;
        #pragma unroll
        for (int kk = 0; kk < 8; kk++) {
            #pragma unroll
            for (int j = 0; j < 8; j++) {
                const int colb = j * 8 + gr;
                float bv0 = Sts[(kk * 8 + tg) * ST_STRIDE + colb];
                float bv1 = Sts[(kk * 8 + tg + 4) * ST_STRIDE + colb];
                unsigned b0h = f2tf(bv0), b1h = f2tf(bv1);
                unsigned b0l = f2tf(bv0 - __uint_as_float(b0h));
                unsigned b1l = f2tf(bv1 - __uint_as_float(b1h));
                mma_tf32(OaI[j], qA[kk].x, qB[kk].x, qA[kk].y, qB[kk].y, b0h, b1h);
                mma_tf32(OaI[j], qA[kk].x, qB[kk].x, qA[kk].y, qB[kk].y, b0l, b1l);
            }
        }
        const float s0 = exp2f((float)(row0 + gr) * l2g);
        const float s1 = exp2f((float)(row0 + gr + 8) * l2g);
        #pragma unroll
        for (int j = 0; j < 8; j++) {
            Oa[j][0] += s0 * OaI[j][0]; Oa[j][1] += s0 * OaI[j][1];
            Oa[j][2] += s1 * OaI[j][2]; Oa[j][3] += s1 * OaI[j][3];
        }
    }

    // ---- write O directly (warp owns all keys; no reduction) ----
    #pragma unroll
    for (int j = 0; j < 8; j++) {
        const int c = j * 8 + tg * 2;
        *(float2*)(Og + (size_t)r0 * DHn + c) = make_float2(Oa[j][0], Oa[j][1]);
        *(float2*)(Og + (size_t)r1 * DHn + c) = make_float2(Oa[j][2], Oa[j][3]);
    }

    // ---- zero-fill masked MSR tiles ----
    {
        const int nzt = 15 - qblk;
        if (nzt > 0) {
            const int c0z = (qblk + 1) * BN;
            const float4 z = make_float4(0.f, 0.f, 0.f, 0.f);
            const int nf4 = nzt * 32;
            for (int r = warp; r < BM; r += 8) {
                float* row = Mg + (size_t)r * Sn + c0z;
                for (int t = lane; t < nf4; t += 32)
                    *(float4*)(row + t * 4) = z;
            }
        }
    }
}

extern "C" void kernel_launch(void* const* d_in, const int* in_sizes, int n_in,
                              void* d_out, int out_size) {
    const float* Q = (const float*)d_in[0];
    const float* K = (const float*)d_in[1];
    const float* V = (const float*)d_in[2];
    // d_in[3] = D  (computed analytically in-kernel)

    float* out = (float*)d_out;                                  // [B,H,S,DH]
    float* msr = out + (size_t)Bsz * Hn * Sn * DHn;              // [B,H,S,S]

    const size_t smemA = (size_t)(2 * BN * 72) * sizeof(float);
    cudaFuncSetAttribute(state_tiles_kernel,
                         cudaFuncAttributeMaxDynamicSharedMemorySize, (int)smemA);
    const size_t smemC = (size_t)(2 * BM * KS_STRIDE + DHn * ST_STRIDE) * sizeof(float);
    cudaFuncSetAttribute(retnet_msr_kernel,
                         cudaFuncAttributeMaxDynamicSharedMemorySize, (int)smemC);

    state_tiles_kernel<<<dim3(NT, Bsz * Hn), 256, smemA>>>(K, V);
    retnet_msr_kernel<<<dim3(Sn / BM, Bsz * Hn), THREADS, smemC>>>(Q, K, V, out, msr);
}